// round 10
// baseline (speedup 1.0000x reference)
#include <cuda_runtime.h>
#include <cuda_bf16.h>
#include <cstdint>

#define NN 32768
#define KK 8192
#define DD 512
#define CAP (1 << 21)
// margin in int-dot domain = 6e-4 * 127*127*8192 / 2 / rowmax = 39638.6/rowmax
#define MARGIN_NUM 39639.0f

// ======================= PTX helpers (compute_103-safe) ===================
__device__ __forceinline__ uint32_t smem_to_u32(const void* p) {
    uint32_t a;
    asm("{ .reg .u64 t; cvta.to.shared.u64 t, %1; cvt.u32.u64 %0, t; }"
        : "=r"(a) : "l"(p));
    return a;
}
__device__ __forceinline__ void ldsm_x4(uint32_t* r, uint32_t addr) {
    asm volatile("ldmatrix.sync.aligned.m8n8.x4.shared.b16 {%0,%1,%2,%3}, [%4];"
        : "=r"(r[0]), "=r"(r[1]), "=r"(r[2]), "=r"(r[3]) : "r"(addr));
}
__device__ __forceinline__ void ldsm_x2(uint32_t* r, uint32_t addr) {
    asm volatile("ldmatrix.sync.aligned.m8n8.x2.shared.b16 {%0,%1}, [%2];"
        : "=r"(r[0]), "=r"(r[1]) : "r"(addr));
}
__device__ __forceinline__ void mma16832_s8(int* d, const uint32_t* a, const uint32_t* b) {
    asm volatile("mma.sync.aligned.m16n8k32.row.col.s32.s8.s8.s32 "
        "{%0,%1,%2,%3}, {%4,%5,%6,%7}, {%8,%9}, {%0,%1,%2,%3};"
        : "+r"(d[0]), "+r"(d[1]), "+r"(d[2]), "+r"(d[3])
        : "r"(a[0]), "r"(a[1]), "r"(a[2]), "r"(a[3]), "r"(b[0]), "r"(b[1]));
}
__device__ __forceinline__ void cpasync16(uint32_t dst, const void* src) {
    asm volatile("cp.async.cg.shared.global [%0], [%1], 16;" :: "r"(dst), "l"(src));
}
#define CP_COMMIT() asm volatile("cp.async.commit_group;" ::: "memory")
#define CP_WAIT(n)  asm volatile("cp.async.wait_group %0;" :: "n"(n) : "memory")

// ======================= device scratch ===================================
__device__ __align__(16) signed char g_zq[(size_t)NN * DD];  // int8 z (per-row scale)
__device__ __align__(16) signed char g_eq[(size_t)KK * DD];  // int8 e (scale 127*8192)
__device__ float               g_sz[NN];
__device__ float               g_zmax[NN];
__device__ float               g_se[KK];
__device__ unsigned long long  g_best[NN];      // (distbits<<32)|k
__device__ int                 g_idx[NN];
__device__ int                 g_ncand;
__device__ int2                g_cand[CAP];
__device__ double              g_losssum;

// ======================= init =============================================
__global__ void vq_init()
{
    int i = blockIdx.x * 256 + threadIdx.x;
    if (i < NN) g_best[i] = 0xFFFFFFFFFFFFFFFFull;
    if (i == 0) { g_losssum = 0.0; g_ncand = 0; }
}

// ======================= prep: sumsq + rowmax + int8 quantize =============
__device__ __forceinline__ uint32_t pack4(float4 v, float sc) {
    int a = __float2int_rn(v.x * sc), b = __float2int_rn(v.y * sc);
    int c = __float2int_rn(v.z * sc), d = __float2int_rn(v.w * sc);
    return (a & 0xff) | ((b & 0xff) << 8) | ((c & 0xff) << 16) | ((d & 0xff) << 24);
}
__device__ __forceinline__ double sq4(float4 v) {
    return (double)v.x * v.x + (double)v.y * v.y
         + (double)v.z * v.z + (double)v.w * v.w;
}
__device__ __forceinline__ float amax4(float4 v) {
    return fmaxf(fmaxf(fabsf(v.x), fabsf(v.y)), fmaxf(fabsf(v.z), fabsf(v.w)));
}

__global__ void vq_prep_z(const float* __restrict__ z)
{
    int row  = blockIdx.x * 8 + (threadIdx.x >> 5);
    int lane = threadIdx.x & 31;
    const float4* zr = (const float4*)(z + (size_t)row * DD) + lane * 4;
    float4 v0 = zr[0], v1 = zr[1], v2 = zr[2], v3 = zr[3];
    double s0 = sq4(v0), s1 = sq4(v1), s2 = sq4(v2), s3 = sq4(v3);
    float mx = fmaxf(fmaxf(amax4(v0), amax4(v1)), fmaxf(amax4(v2), amax4(v3)));
    double s = (s0 + s1) + (s2 + s3);
    #pragma unroll
    for (int o = 16; o >= 1; o >>= 1) {
        s  += __shfl_xor_sync(0xffffffffu, s, o);
        mx  = fmaxf(mx, __shfl_xor_sync(0xffffffffu, mx, o));
    }
    if (lane == 0) { g_sz[row] = (float)s; g_zmax[row] = mx; }
    float sc = (mx > 0.0f) ? 127.0f / mx : 0.0f;
    uint4 p = make_uint4(pack4(v0, sc), pack4(v1, sc), pack4(v2, sc), pack4(v3, sc));
    *(uint4*)(g_zq + (size_t)row * DD + lane * 16) = p;
}

__global__ void vq_prep_e(const float* __restrict__ e)
{
    int row  = blockIdx.x * 8 + (threadIdx.x >> 5);
    int lane = threadIdx.x & 31;
    const float4* er = (const float4*)(e + (size_t)row * DD) + lane * 4;
    float4 v0 = er[0], v1 = er[1], v2 = er[2], v3 = er[3];
    double s0 = sq4(v0), s1 = sq4(v1), s2 = sq4(v2), s3 = sq4(v3);
    double s = (s0 + s1) + (s2 + s3);
    #pragma unroll
    for (int o = 16; o >= 1; o >>= 1)
        s += __shfl_xor_sync(0xffffffffu, s, o);
    if (lane == 0) g_se[row] = (float)s;
    const float sc = 127.0f * 8192.0f;
    uint4 p = make_uint4(pack4(v0, sc), pack4(v1, sc), pack4(v2, sc), pack4(v3, sc));
    *(uint4*)(g_eq + (size_t)row * DD + lane * 16) = p;
}

// ======================= IMMA GEMM + candidate scan =======================
// CTA: 512 thr = 16 warps (2M x 8N). CTA tile 128 rows x 256 codebook cols,
// full D=512. Warp tile 64x32, mma m16n8k32.s8 (exact int arithmetic).
// A (z int8 tile, 64 KB) resident; B streamed in 128-byte-depth chunks
// (32 KB), double buffered cp.async. Epilogue per tile: per-row running max
// of idot, then scan idot >= runmax - margin_int(row) -> candidates.
#define SM_A   0
#define SM_B0  65536
#define SM_B1  (65536 + 32768)
#define SM_RT  (65536 + 65536)              /* rowtile: 128*8 int  = 4KB */
#define SM_RM  (SM_RT + 4096)               /* running rowmax: 128 int   */
#define SM_MG  (SM_RM + 512)                /* margin per row: 128 int   */
#define SMEMSZ (SM_MG + 512)

__global__ void __launch_bounds__(512, 1) vq_mma_i8()
{
    extern __shared__ char smem[];
    const int tid    = threadIdx.x;
    const int wid    = tid >> 5, lane = tid & 31;
    const int warp_m = wid >> 3, warp_n = wid & 7;
    const int m0     = blockIdx.x * 128;
    const uint32_t sb = smem_to_u32(smem);
    int* rowtile  = (int*)(smem + SM_RT);
    int* s_rowmax = (int*)(smem + SM_RM);
    int* s_margin = (int*)(smem + SM_MG);

    // ---- load A (z int8 tile) resident, swizzle unit c ^= row&7 ----
    for (int i = tid; i < 4096; i += 512) {
        int r = i >> 5, c = i & 31;
        uint4 v = *((const uint4*)(g_zq + (size_t)(m0 + r) * DD) + c);
        *(uint4*)(smem + SM_A + r * 512 + ((c ^ (r & 7)) << 4)) = v;
    }
    if (tid < 128) {
        s_rowmax[tid] = (int)0x80000000;
        float mx = g_zmax[m0 + tid];
        s_margin[tid] = (int)fminf(MARGIN_NUM / fmaxf(mx, 1e-6f), 2.0e9f);
    }
    __syncthreads();

    // ---- ldmatrix address precompute ----
    const int mat = lane >> 3, rq = lane & 7;
    const uint32_t a_mathi = (uint32_t)(mat >> 1);
    uint32_t a_base[4];
    #pragma unroll
    for (int mt = 0; mt < 4; mt++) {
        int row = warp_m * 64 + mt * 16 + (mat & 1) * 8 + rq;
        a_base[mt] = sb + SM_A + row * 512;
    }
    const int tb = lane & 15, matb = tb >> 3, rbq = tb & 7;
    uint32_t b_base[4];
    #pragma unroll
    for (int n4 = 0; n4 < 4; n4++)
        b_base[n4] = (uint32_t)((warp_n * 32 + n4 * 8 + rbq) * 128);

    #pragma unroll 1
    for (int nt = 0; nt < 32; nt++) {
        const signed char* ebase = g_eq + (size_t)(nt * 256) * DD;

        // prefetch chunk 0 -> buf0   (chunk = 256 rows x 128 depth bytes)
        #pragma unroll
        for (int p = 0; p < 4; p++) {
            int u = tid + p * 512, r = u >> 3, c = u & 7;
            cpasync16(sb + SM_B0 + r * 128 + ((c ^ (r & 7)) << 4),
                      ebase + (size_t)r * DD + c * 16);
        }
        CP_COMMIT();

        int acc[4][4][4];
        #pragma unroll
        for (int mt = 0; mt < 4; mt++)
            #pragma unroll
            for (int n4 = 0; n4 < 4; n4++)
                #pragma unroll
                for (int q = 0; q < 4; q++) acc[mt][n4][q] = 0;

        #pragma unroll 1
        for (int ch = 0; ch < 4; ch++) {
            const uint32_t bufb = sb + ((ch & 1) ? SM_B1 : SM_B0);
            if (ch < 3) {
                const uint32_t nbuf = sb + (((ch + 1) & 1) ? SM_B1 : SM_B0);
                const int d0 = (ch + 1) * 128;
                #pragma unroll
                for (int p = 0; p < 4; p++) {
                    int u = tid + p * 512, r = u >> 3, c = u & 7;
                    cpasync16(nbuf + r * 128 + ((c ^ (r & 7)) << 4),
                              ebase + (size_t)r * DD + d0 + c * 16);
                }
                CP_COMMIT();
                CP_WAIT(1);
            } else {
                CP_WAIT(0);
            }
            __syncthreads();

            #pragma unroll
            for (int ks = 0; ks < 4; ks++) {
                const uint32_t ua = (uint32_t)(ch * 8 + ks * 2) + a_mathi;
                uint32_t afrag[4][4], bfrag[4][2];
                #pragma unroll
                for (int mt = 0; mt < 4; mt++)
                    ldsm_x4(afrag[mt], a_base[mt] + ((ua ^ (uint32_t)rq) << 4));
                #pragma unroll
                for (int n4 = 0; n4 < 4; n4++)
                    ldsm_x2(bfrag[n4], bufb + b_base[n4]
                            + ((((uint32_t)(ks << 1) + matb) ^ (uint32_t)rbq) << 4));
                #pragma unroll
                for (int mt = 0; mt < 4; mt++)
                    #pragma unroll
                    for (int n4 = 0; n4 < 4; n4++)
                        mma16832_s8(acc[mt][n4], afrag[mt], bfrag[n4]);
            }
            __syncthreads();
        }

        // ---- epilogue: per-row running max of idot, then candidate scan --
        #pragma unroll
        for (int mt = 0; mt < 4; mt++)
            #pragma unroll
            for (int h = 0; h < 2; h++) {
                int m = (int)0x80000000;
                #pragma unroll
                for (int n4 = 0; n4 < 4; n4++)
                    m = max(m, max(acc[mt][n4][2 * h], acc[mt][n4][2 * h + 1]));
                m = max(m, __shfl_xor_sync(0xffffffffu, m, 1));
                m = max(m, __shfl_xor_sync(0xffffffffu, m, 2));
                if ((lane & 3) == 0) {
                    int rl = warp_m * 64 + mt * 16 + (lane >> 2) + 8 * h;
                    rowtile[rl * 8 + warp_n] = m;
                }
            }
        __syncthreads();
        if (tid < 128) {
            int m = rowtile[tid * 8];
            #pragma unroll
            for (int q = 1; q < 8; q++) m = max(m, rowtile[tid * 8 + q]);
            s_rowmax[tid] = max(s_rowmax[tid], m);
        }
        __syncthreads();
        #pragma unroll
        for (int mt = 0; mt < 4; mt++)
            #pragma unroll
            for (int h = 0; h < 2; h++) {
                int rl = warp_m * 64 + mt * 16 + (lane >> 2) + 8 * h;
                long long thr = (long long)s_rowmax[rl] - (long long)s_margin[rl];
                #pragma unroll
                for (int n4 = 0; n4 < 4; n4++)
                    #pragma unroll
                    for (int j = 0; j < 2; j++) {
                        if ((long long)acc[mt][n4][2 * h + j] >= thr) {
                            int col = nt * 256 + warp_n * 32 + n4 * 8 + 2 * (lane & 3) + j;
                            int pos = atomicAdd(&g_ncand, 1);
                            if (pos < CAP) g_cand[pos] = make_int2(m0 + rl, col);
                        }
                    }
            }
        __syncthreads();
    }
}

// ======================= exact rescue (reference-rounded) =================
__global__ void vq_recheck(const float* __restrict__ z, const float* __restrict__ e)
{
    int i = blockIdx.x * 256 + threadIdx.x;
    int n = g_ncand; if (n > CAP) n = CAP;
    if (i >= n) return;
    int2 cd = g_cand[i];
    int row = cd.x, k = cd.y;
    const float4* zr = (const float4*)(z + (size_t)row * DD);
    const float4* er = (const float4*)(e + (size_t)k * DD);
    float acc = 0.0f;
    #pragma unroll 8
    for (int j = 0; j < DD / 4; j++) {
        float4 a = zr[j], b = er[j];
        acc = fmaf(a.x, b.x, acc);
        acc = fmaf(a.y, b.y, acc);
        acc = fmaf(a.z, b.z, acc);
        acc = fmaf(a.w, b.w, acc);
    }
    float A = g_sz[row] + g_se[k];
    float dist = A - 2.0f * acc;
    unsigned long long key =
        (((unsigned long long)__float_as_uint(dist)) << 32) | (unsigned)k;
    atomicMin(&g_best[row], key);
}

// ======================= gather + STE + loss ==============================
__global__ void vq_gather(const float* __restrict__ z, const float* __restrict__ e,
                          float* __restrict__ out, int write_q)
{
    __shared__ double warpsum[4];
    int row = blockIdx.x;
    int t   = threadIdx.x;                    // 0..127
    int k   = (int)(g_best[row] & 0xffffffffull);
    if (t == 0) g_idx[row] = k;
    float4 q  = ((const float4*)(e + (size_t)k   * DD))[t];
    float4 zz = ((const float4*)(z + (size_t)row * DD))[t];
    float d0 = q.x - zz.x, d1 = q.y - zz.y, d2 = q.z - zz.z, d3 = q.w - zz.w;
    if (write_q) {
        float4 o = make_float4(zz.x + d0, zz.y + d1, zz.z + d2, zz.w + d3);
        ((float4*)out)[(size_t)row * (DD / 4) + t] = o;
    }
    float s0 = d0 * d0, s1 = d1 * d1, s2 = d2 * d2, s3 = d3 * d3;
    double s = (double)s0 + (double)s1 + (double)s2 + (double)s3;
    #pragma unroll
    for (int o = 16; o >= 1; o >>= 1)
        s += __shfl_down_sync(0xffffffffu, s, o);
    if ((t & 31) == 0) warpsum[t >> 5] = s;
    __syncthreads();
    if (t == 0) {
        double tot = warpsum[0] + warpsum[1] + warpsum[2] + warpsum[3];
        atomicAdd(&g_losssum, tot);
    }
}

// ======================= tail / alt outputs ===============================
__global__ void vq_tail(float* __restrict__ out, long long out_size,
                        long long loss_pos, long long idx_base)
{
    long long pos = (long long)NN * DD + (long long)blockIdx.x * 256 + threadIdx.x;
    if (pos >= out_size) return;
    if (pos == loss_pos) {
        float m = (float)(g_losssum / (double)((long long)NN * DD));
        out[pos] = m + 0.25f * m;
    } else if (idx_base >= 0 && pos >= idx_base && pos < idx_base + NN) {
        out[pos] = (float)g_idx[pos - idx_base];
    } else {
        out[pos] = 0.0f;
    }
}
__global__ void vq_idx_int(int* __restrict__ out)
{
    int i = blockIdx.x * 256 + threadIdx.x;
    if (i < NN) out[i] = g_idx[i];
}
__global__ void vq_loss_only(float* __restrict__ out)
{
    float m = (float)(g_losssum / (double)((long long)NN * DD));
    out[0] = m + 0.25f * m;
}

// ======================= launch ===========================================
extern "C" void kernel_launch(void* const* d_in, const int* in_sizes, int n_in,
                              void* d_out, int out_size)
{
    const float* z = nullptr;
    const float* e = nullptr;
    for (int i = 0; i < n_in; i++) {
        if      (in_sizes[i] == NN * DD) z = (const float*)d_in[i];
        else if (in_sizes[i] == KK * DD) e = (const float*)d_in[i];
    }
    if (!z) z = (const float*)d_in[0];
    if (!e) e = (const float*)d_in[1];

    cudaFuncSetAttribute(vq_mma_i8, cudaFuncAttributeMaxDynamicSharedMemorySize, SMEMSZ);

    vq_init<<<NN / 256, 256>>>();
    vq_prep_z<<<NN / 8, 256>>>(z);
    vq_prep_e<<<KK / 8, 256>>>(e);
    vq_mma_i8<<<NN / 128, 512, SMEMSZ>>>();
    vq_recheck<<<CAP / 256, 256>>>(z, e);

    const long long QD = (long long)NN * DD;   // 16777216
    long long OS = (long long)out_size;

    if (OS >= QD) {
        vq_gather<<<NN, 128>>>(z, e, (float*)d_out, 1);
        long long rem = OS - QD;
        if (rem > 0) {
            long long loss_pos = -1, idx_base = -1;
            if (rem >= 1 + (long long)NN) { loss_pos = QD; idx_base = QD + 1; }
            else if (rem == (long long)NN) { idx_base = QD; }
            else { loss_pos = QD; }
            int blocks = (int)((rem + 255) / 256);
            vq_tail<<<blocks, 256>>>((float*)d_out, OS, loss_pos, idx_base);
        }
    } else if (OS == NN) {
        vq_gather<<<NN, 128>>>(z, e, nullptr, 0);
        vq_idx_int<<<NN / 256, 256>>>((int*)d_out);
    } else if (OS == 1) {
        vq_gather<<<NN, 128>>>(z, e, nullptr, 0);
        vq_loss_only<<<1, 1>>>((float*)d_out);
    } else {
        vq_gather<<<NN, 128>>>(z, e, nullptr, 0);
    }
}

// round 14
// speedup vs baseline: 1.4740x; 1.4740x over previous
#include <cuda_runtime.h>
#include <cuda_fp16.h>
#include <cstdint>

#define NN 32768
#define KK 8192
#define DD 512
#define CAP (1 << 21)

// ======================= PTX helpers (compute_103-safe) ===================
__device__ __forceinline__ uint32_t smem_to_u32(const void* p) {
    uint32_t a;
    asm("{ .reg .u64 t; cvta.to.shared.u64 t, %1; cvt.u32.u64 %0, t; }"
        : "=r"(a) : "l"(p));
    return a;
}
__device__ __forceinline__ void ldsm_x4(uint32_t* r, uint32_t addr) {
    asm volatile("ldmatrix.sync.aligned.m8n8.x4.shared.b16 {%0,%1,%2,%3}, [%4];"
        : "=r"(r[0]), "=r"(r[1]), "=r"(r[2]), "=r"(r[3]) : "r"(addr));
}
__device__ __forceinline__ void ldsm_x2(uint32_t* r, uint32_t addr) {
    asm volatile("ldmatrix.sync.aligned.m8n8.x2.shared.b16 {%0,%1}, [%2];"
        : "=r"(r[0]), "=r"(r[1]) : "r"(addr));
}
// fp16 accumulate HMMA
__device__ __forceinline__ void mma16816_f16(uint32_t* d, const uint32_t* a, const uint32_t* b) {
    asm volatile("mma.sync.aligned.m16n8k16.row.col.f16.f16.f16.f16 "
        "{%0,%1}, {%2,%3,%4,%5}, {%6,%7}, {%0,%1};"
        : "+r"(d[0]), "+r"(d[1])
        : "r"(a[0]), "r"(a[1]), "r"(a[2]), "r"(a[3]), "r"(b[0]), "r"(b[1]));
}
__device__ __forceinline__ void cpasync16(uint32_t dst, const void* src) {
    asm volatile("cp.async.cg.shared.global [%0], [%1], 16;" :: "r"(dst), "l"(src));
}
#define CP_COMMIT() asm volatile("cp.async.commit_group;" ::: "memory")
#define CP_WAIT(n)  asm volatile("cp.async.wait_group %0;" :: "n"(n) : "memory")

// ======================= device scratch ===================================
__device__ __align__(16) __half g_zh[(size_t)NN * DD];  // z * (4/rowmax)
__device__ __align__(16) __half g_eh[(size_t)KK * DD];  // e * 8192
__device__ float               g_sz[NN];
__device__ float               g_se[KK];
__device__ float               g_margin[NN];   // scaled-dot margin per row
__device__ unsigned long long  g_best[NN];     // (distbits<<32)|k
__device__ int                 g_idx[NN];
__device__ int                 g_ncand;
__device__ int2                g_cand[CAP];
__device__ double              g_losssum;

// ======================= init =============================================
__global__ void vq_init()
{
    int i = blockIdx.x * 256 + threadIdx.x;
    if (i < NN) g_best[i] = 0xFFFFFFFFFFFFFFFFull;
    if (i == 0) { g_losssum = 0.0; g_ncand = 0; }
}

// ======================= prep: sumsq + rowmax + fp16 scale ================
__device__ __forceinline__ double sq4(float4 v) {
    return (double)v.x * v.x + (double)v.y * v.y
         + (double)v.z * v.z + (double)v.w * v.w;
}
__device__ __forceinline__ float amax4(float4 v) {
    return fmaxf(fmaxf(fabsf(v.x), fabsf(v.y)), fmaxf(fabsf(v.z), fabsf(v.w)));
}
__device__ __forceinline__ uint32_t h2pack(float a, float b) {
    __half2 t = __floats2half2_rn(a, b);
    return *(uint32_t*)&t;
}
__device__ __forceinline__ void pack8(uint32_t* q, float4 a, float4 b, float sc) {
    q[0] = h2pack(a.x * sc, a.y * sc);
    q[1] = h2pack(a.z * sc, a.w * sc);
    q[2] = h2pack(b.x * sc, b.y * sc);
    q[3] = h2pack(b.z * sc, b.w * sc);
}

__global__ void vq_prep_z(const float* __restrict__ z)
{
    int row  = blockIdx.x * 8 + (threadIdx.x >> 5);
    int lane = threadIdx.x & 31;
    const float4* zr = (const float4*)(z + (size_t)row * DD) + lane * 4;
    float4 v0 = zr[0], v1 = zr[1], v2 = zr[2], v3 = zr[3];
    double s0 = sq4(v0), s1 = sq4(v1), s2 = sq4(v2), s3 = sq4(v3);
    float mx = fmaxf(fmaxf(amax4(v0), amax4(v1)), fmaxf(amax4(v2), amax4(v3)));
    double s = (s0 + s1) + (s2 + s3);
    #pragma unroll
    for (int o = 16; o >= 1; o >>= 1) {
        s  += __shfl_xor_sync(0xffffffffu, s, o);
        mx  = fmaxf(mx, __shfl_xor_sync(0xffffffffu, mx, o));
    }
    mx = fmaxf(mx, 1e-20f);
    if (lane == 0) {
        g_sz[row] = (float)s;
        // dist-domain margin 1.2e-3 -> dot margin 6e-4; scale (4/mx)*8192
        g_margin[row] = 6e-4f * (4.0f / mx) * 8192.0f;
    }
    float sc = 4.0f / mx;
    uint32_t q[8];
    pack8(q,     v0, v1, sc);
    pack8(q + 4, v2, v3, sc);
    uint4* dst = (uint4*)(g_zh + (size_t)row * DD + lane * 16);
    dst[0] = make_uint4(q[0], q[1], q[2], q[3]);
    dst[1] = make_uint4(q[4], q[5], q[6], q[7]);
}

__global__ void vq_prep_e(const float* __restrict__ e)
{
    int row  = blockIdx.x * 8 + (threadIdx.x >> 5);
    int lane = threadIdx.x & 31;
    const float4* er = (const float4*)(e + (size_t)row * DD) + lane * 4;
    float4 v0 = er[0], v1 = er[1], v2 = er[2], v3 = er[3];
    double s0 = sq4(v0), s1 = sq4(v1), s2 = sq4(v2), s3 = sq4(v3);
    double s = (s0 + s1) + (s2 + s3);
    #pragma unroll
    for (int o = 16; o >= 1; o >>= 1)
        s += __shfl_xor_sync(0xffffffffu, s, o);
    if (lane == 0) g_se[row] = (float)s;
    const float sc = 8192.0f;
    uint32_t q[8];
    pack8(q,     v0, v1, sc);
    pack8(q + 4, v2, v3, sc);
    uint4* dst = (uint4*)(g_eh + (size_t)row * DD + lane * 16);
    dst[0] = make_uint4(q[0], q[1], q[2], q[3]);
    dst[1] = make_uint4(q[4], q[5], q[6], q[7]);
}

// ======================= HMMA-f16 GEMM + candidate scan ===================
// 512 thr = 16 warps (2M x 8N). CTA tile 128 x 256, warp tile 64 x 32.
// A resident in smem (128 KB). B: 3-stage cp.async ring, stage = 256 cols x
// 32 depth fp16 (80B padded rows), ONE __syncthreads per stage. Flattened
// stage loop g=0..511 (nt = g/16). Epilogue per nt: per-row running max of
// scaled dot, candidate scan vs rowmax - margin.
#define SM_A     0
#define SM_B     131072
#define STG_B    20480                        /* 256 * 80 */
#define SM_RT    (131072 + 3 * STG_B)         /* 192512: 128*8 floats */
#define SM_RM    (SM_RT + 4096)
#define SM_MG    (SM_RM + 512)
#define SMEMSZ   (SM_MG + 512)

__global__ void __launch_bounds__(512, 1) vq_mma_h()
{
    extern __shared__ char smem[];
    const int tid    = threadIdx.x;
    const int wid    = tid >> 5, lane = tid & 31;
    const int warp_m = wid >> 3, warp_n = wid & 7;
    const int m0     = blockIdx.x * 128;
    const uint32_t sb = smem_to_u32(smem);
    float* rowtile  = (float*)(smem + SM_RT);
    float* s_rowmax = (float*)(smem + SM_RM);
    float* s_margin = (float*)(smem + SM_MG);

    // ---- A resident: 128 rows x 512 fp16 (1024 B rows), unit swizzle ----
    for (int i = tid; i < 8192; i += 512) {
        int r = i >> 6, c = i & 63;
        uint4 v = *((const uint4*)(g_zh + (size_t)(m0 + r) * DD) + c);
        *(uint4*)(smem + SM_A + r * 1024 + ((c ^ (r & 7)) << 4)) = v;
    }
    if (tid < 128) {
        s_rowmax[tid] = -3.4e38f;
        s_margin[tid] = g_margin[m0 + tid];
    }

    // ---- ldmatrix address precompute (proven R9 scheme) ----
    const int mat = lane >> 3, rq = lane & 7;
    const uint32_t a_hi = (uint32_t)((mat >> 1) << 4);
    uint32_t a_row[4], a_x[4];
    #pragma unroll
    for (int mt = 0; mt < 4; mt++) {
        int rg = warp_m * 64 + mt * 16 + (mat & 1) * 8 + rq;
        a_row[mt] = sb + SM_A + rg * 1024;
        a_x[mt]   = (uint32_t)((rg & 7) << 4);
    }
    const int tb = lane & 15, matb = tb >> 3, rbq = tb & 7;
    uint32_t b_off[4];
    #pragma unroll
    for (int n4 = 0; n4 < 4; n4++)
        b_off[n4] = (uint32_t)((warp_n * 32 + n4 * 8 + rbq) * 80 + (matb << 4));

    // ---- cp.async stage issue (256 rows x 64 B, 2 chunks/thread) ----
    auto issue_stage = [&](int g) {
        int nt = g >> 4, d0 = (g & 15) * 32;
        const __half* eb = g_eh + (size_t)(nt * 256) * DD + d0;
        uint32_t dst = sb + SM_B + (g % 3) * STG_B;
        #pragma unroll
        for (int p = 0; p < 2; p++) {
            int u = tid + p * 512, r = u >> 2, c = u & 3;
            cpasync16(dst + r * 80 + (c << 4), eb + (size_t)r * DD + c * 8);
        }
    };

    issue_stage(0); CP_COMMIT();
    issue_stage(1); CP_COMMIT();

    uint32_t acc[4][4][2];
    #pragma unroll
    for (int mt = 0; mt < 4; mt++)
        #pragma unroll
        for (int n4 = 0; n4 < 4; n4++) { acc[mt][n4][0] = 0u; acc[mt][n4][1] = 0u; }

    #pragma unroll 1
    for (int g = 0; g < 512; g++) {
        CP_WAIT(1);
        __syncthreads();
        if (g + 2 < 512) issue_stage(g + 2);
        CP_COMMIT();

        const uint32_t bufb = sb + SM_B + (g % 3) * STG_B;
        #pragma unroll
        for (int ks = 0; ks < 2; ks++) {
            const uint32_t au = (uint32_t)(((g & 15) * 4 + ks * 2) << 4);
            uint32_t afrag[4][4], bfrag[4][2];
            #pragma unroll
            for (int mt = 0; mt < 4; mt++)
                ldsm_x4(afrag[mt], a_row[mt] + ((au + a_hi) ^ a_x[mt]));
            #pragma unroll
            for (int n4 = 0; n4 < 4; n4++)
                ldsm_x2(bfrag[n4], bufb + b_off[n4] + (ks << 5));
            #pragma unroll
            for (int mt = 0; mt < 4; mt++)
                #pragma unroll
                for (int n4 = 0; n4 < 4; n4++)
                    mma16816_f16(acc[mt][n4], afrag[mt], bfrag[n4]);
        }

        if ((g & 15) == 15) {
            const int nt = g >> 4;
            // per-row max within thread/quad
            #pragma unroll
            for (int mt = 0; mt < 4; mt++)
                #pragma unroll
                for (int h = 0; h < 2; h++) {
                    float m = -3.4e38f;
                    #pragma unroll
                    for (int n4 = 0; n4 < 4; n4++) {
                        float2 v = __half22float2(*(__half2*)&acc[mt][n4][h]);
                        m = fmaxf(m, fmaxf(v.x, v.y));
                    }
                    m = fmaxf(m, __shfl_xor_sync(0xffffffffu, m, 1));
                    m = fmaxf(m, __shfl_xor_sync(0xffffffffu, m, 2));
                    if ((lane & 3) == 0) {
                        int rl = warp_m * 64 + mt * 16 + (lane >> 2) + 8 * h;
                        rowtile[rl * 8 + warp_n] = m;
                    }
                }
            __syncthreads();
            if (tid < 128) {
                float m = rowtile[tid * 8];
                #pragma unroll
                for (int q = 1; q < 8; q++) m = fmaxf(m, rowtile[tid * 8 + q]);
                s_rowmax[tid] = fmaxf(s_rowmax[tid], m);
            }
            __syncthreads();
            #pragma unroll
            for (int mt = 0; mt < 4; mt++)
                #pragma unroll
                for (int h = 0; h < 2; h++) {
                    int rl = warp_m * 64 + mt * 16 + (lane >> 2) + 8 * h;
                    float thr = s_rowmax[rl] - s_margin[rl];
                    #pragma unroll
                    for (int n4 = 0; n4 < 4; n4++) {
                        float2 v = __half22float2(*(__half2*)&acc[mt][n4][h]);
                        #pragma unroll
                        for (int j = 0; j < 2; j++) {
                            float vv = j ? v.y : v.x;
                            if (vv >= thr) {
                                int col = nt * 256 + warp_n * 32 + n4 * 8
                                        + 2 * (lane & 3) + j;
                                int pos = atomicAdd(&g_ncand, 1);
                                if (pos < CAP) g_cand[pos] = make_int2(m0 + rl, col);
                            }
                        }
                        acc[mt][n4][h] = 0u;   // reset for next nt
                    }
                }
        }
    }
}

// ======================= exact rescue (reference-rounded) =================
__global__ void vq_recheck(const float* __restrict__ z, const float* __restrict__ e)
{
    int i = blockIdx.x * 256 + threadIdx.x;
    int n = g_ncand; if (n > CAP) n = CAP;
    if (i >= n) return;
    int2 cd = g_cand[i];
    int row = cd.x, k = cd.y;
    const float4* zr = (const float4*)(z + (size_t)row * DD);
    const float4* er = (const float4*)(e + (size_t)k * DD);
    float acc = 0.0f;
    #pragma unroll 8
    for (int j = 0; j < DD / 4; j++) {
        float4 a = zr[j], b = er[j];
        acc = fmaf(a.x, b.x, acc);
        acc = fmaf(a.y, b.y, acc);
        acc = fmaf(a.z, b.z, acc);
        acc = fmaf(a.w, b.w, acc);
    }
    float A = g_sz[row] + g_se[k];
    float dist = A - 2.0f * acc;
    unsigned long long key =
        (((unsigned long long)__float_as_uint(dist)) << 32) | (unsigned)k;
    atomicMin(&g_best[row], key);
}

// ======================= gather + STE + loss ==============================
__global__ void vq_gather(const float* __restrict__ z, const float* __restrict__ e,
                          float* __restrict__ out, int write_q)
{
    __shared__ double warpsum[4];
    int row = blockIdx.x;
    int t   = threadIdx.x;                    // 0..127
    int k   = (int)(g_best[row] & 0xffffffffull);
    if (t == 0) g_idx[row] = k;
    float4 q  = ((const float4*)(e + (size_t)k   * DD))[t];
    float4 zz = ((const float4*)(z + (size_t)row * DD))[t];
    float d0 = q.x - zz.x, d1 = q.y - zz.y, d2 = q.z - zz.z, d3 = q.w - zz.w;
    if (write_q) {
        float4 o = make_float4(zz.x + d0, zz.y + d1, zz.z + d2, zz.w + d3);
        ((float4*)out)[(size_t)row * (DD / 4) + t] = o;
    }
    float s0 = d0 * d0, s1 = d1 * d1, s2 = d2 * d2, s3 = d3 * d3;
    double s = (double)s0 + (double)s1 + (double)s2 + (double)s3;
    #pragma unroll
    for (int o = 16; o >= 1; o >>= 1)
        s += __shfl_down_sync(0xffffffffu, s, o);
    if ((t & 31) == 0) warpsum[t >> 5] = s;
    __syncthreads();
    if (t == 0) {
        double tot = warpsum[0] + warpsum[1] + warpsum[2] + warpsum[3];
        atomicAdd(&g_losssum, tot);
    }
}

// ======================= tail / alt outputs ===============================
__global__ void vq_tail(float* __restrict__ out, long long out_size,
                        long long loss_pos, long long idx_base)
{
    long long pos = (long long)NN * DD + (long long)blockIdx.x * 256 + threadIdx.x;
    if (pos >= out_size) return;
    if (pos == loss_pos) {
        float m = (float)(g_losssum / (double)((long long)NN * DD));
        out[pos] = m + 0.25f * m;
    } else if (idx_base >= 0 && pos >= idx_base && pos < idx_base + NN) {
        out[pos] = (float)g_idx[pos - idx_base];
    } else {
        out[pos] = 0.0f;
    }
}
__global__ void vq_idx_int(int* __restrict__ out)
{
    int i = blockIdx.x * 256 + threadIdx.x;
    if (i < NN) out[i] = g_idx[i];
}
__global__ void vq_loss_only(float* __restrict__ out)
{
    float m = (float)(g_losssum / (double)((long long)NN * DD));
    out[0] = m + 0.25f * m;
}

// ======================= launch ===========================================
extern "C" void kernel_launch(void* const* d_in, const int* in_sizes, int n_in,
                              void* d_out, int out_size)
{
    const float* z = nullptr;
    const float* e = nullptr;
    for (int i = 0; i < n_in; i++) {
        if      (in_sizes[i] == NN * DD) z = (const float*)d_in[i];
        else if (in_sizes[i] == KK * DD) e = (const float*)d_in[i];
    }
    if (!z) z = (const float*)d_in[0];
    if (!e) e = (const float*)d_in[1];

    cudaFuncSetAttribute(vq_mma_h, cudaFuncAttributeMaxDynamicSharedMemorySize, SMEMSZ);

    vq_init<<<NN / 256, 256>>>();
    vq_prep_z<<<NN / 8, 256>>>(z);
    vq_prep_e<<<KK / 8, 256>>>(e);
    vq_mma_h<<<NN / 128, 512, SMEMSZ>>>();
    vq_recheck<<<CAP / 256, 256>>>(z, e);

    const long long QD = (long long)NN * DD;   // 16777216
    long long OS = (long long)out_size;

    if (OS >= QD) {
        vq_gather<<<NN, 128>>>(z, e, (float*)d_out, 1);
        long long rem = OS - QD;
        if (rem > 0) {
            long long loss_pos = -1, idx_base = -1;
            if (rem >= 1 + (long long)NN) { loss_pos = QD; idx_base = QD + 1; }
            else if (rem == (long long)NN) { idx_base = QD; }
            else { loss_pos = QD; }
            int blocks = (int)((rem + 255) / 256);
            vq_tail<<<blocks, 256>>>((float*)d_out, OS, loss_pos, idx_base);
        }
    } else if (OS == NN) {
        vq_gather<<<NN, 128>>>(z, e, nullptr, 0);
        vq_idx_int<<<NN / 256, 256>>>((int*)d_out);
    } else if (OS == 1) {
        vq_gather<<<NN, 128>>>(z, e, nullptr, 0);
        vq_loss_only<<<1, 1>>>((float*)d_out);
    } else {
        vq_gather<<<NN, 128>>>(z, e, nullptr, 0);
    }
}